// round 1
// baseline (speedup 1.0000x reference)
#include <cuda_runtime.h>

#define NN 100000
#define DD 64
#define HH 4096
#define G3H 12288   // 3*HH

// ---------------- scratch (static device globals; no allocation) ----------
__device__ float g_deg[2 * NN];            // [0,N): out_deg (src), [N,2N): in_deg (dst)
__device__ float g_outn[NN];
__device__ float g_inn[NN];
__device__ float g_agg[(size_t)NN * DD];   // aggregation buffer
__device__ float g_h1[(size_t)NN * DD];    // layer-1 output
__device__ float g_gi[2 * G3H];            // W_ih @ [prev1, prev2] + b_ih
__device__ float g_gh[2 * G3H];            // W_hh @ [gc1w, gc2w] + b_hh
__device__ float g_w[2 * HH];              // evolved weights w1, w2 (flat 64x64)

// ---------------- helpers -------------------------------------------------
__device__ __forceinline__ void red_add_f32(float* p, float v) {
    asm volatile("red.global.add.f32 [%0], %1;" :: "l"(p), "f"(v) : "memory");
}
__device__ __forceinline__ void red_add_v4(float* p, float a, float b, float c, float d) {
    asm volatile("red.global.add.v4.f32 [%0], {%1,%2,%3,%4};"
                 :: "l"(p), "f"(a), "f"(b), "f"(c), "f"(d) : "memory");
}

// ---------------- zero kernels -------------------------------------------
__global__ void k_zero_deg(int N) {
    int i = blockIdx.x * blockDim.x + threadIdx.x;
    if (i < 2 * N) g_deg[i] = 0.0f;
}
__global__ void k_zero_agg(int N) {
    int n4 = N * (DD / 4);
    float4* p = (float4*)g_agg;
    int stride = gridDim.x * blockDim.x;
    for (int i = blockIdx.x * blockDim.x + threadIdx.x; i < n4; i += stride)
        p[i] = make_float4(0.f, 0.f, 0.f, 0.f);
}

// ---------------- degrees + norms ----------------------------------------
__global__ void k_degree(const int* __restrict__ src, const int* __restrict__ dst,
                         int E, int N) {
    int stride = gridDim.x * blockDim.x;
    for (int i = blockIdx.x * blockDim.x + threadIdx.x; i < E; i += stride) {
        red_add_f32(&g_deg[src[i]], 1.0f);
        red_add_f32(&g_deg[N + dst[i]], 1.0f);
    }
}
__global__ void k_norm(int N) {
    int i = blockIdx.x * blockDim.x + threadIdx.x;
    if (i < N) {
        g_outn[i] = rsqrtf(fmaxf(g_deg[i], 1.0f));
        g_inn[i]  = rsqrtf(fmaxf(g_deg[N + i], 1.0f));
    }
}

// ---------------- batched GEMV for GRU gates ------------------------------
// Computes gi[b][r] = dot(W_ih[r,:], x_b) + b_ih[r]  (m=0, x = prev_gc1/prev_gc2)
//          gh[b][r] = dot(W_hh[r,:], h_b) + b_hh[r]  (m=1, h = gc1w/gc2w flat)
// One warp per row; both batch vectors read from smem so each 201MB matrix is
// streamed from DRAM exactly once.
__global__ __launch_bounds__(256) void k_gemv(
    const float* __restrict__ W_ih, const float* __restrict__ W_hh,
    const float* __restrict__ xi0, const float* __restrict__ xi1,
    const float* __restrict__ xh0, const float* __restrict__ xh1,
    const float* __restrict__ b_ih, const float* __restrict__ b_hh)
{
    __shared__ float4 xs0[HH / 4];
    __shared__ float4 xs1[HH / 4];

    int nb = gridDim.x >> 1;             // blocks per matrix
    int m  = (blockIdx.x >= nb) ? 1 : 0;
    int bb = blockIdx.x - m * nb;

    const float* W    = m ? W_hh : W_ih;
    const float* xa   = m ? xh0 : xi0;
    const float* xb   = m ? xh1 : xi1;
    const float* bias = m ? b_hh : b_ih;
    float* out        = m ? g_gh : g_gi;

    const float4* xa4 = (const float4*)xa;
    const float4* xb4 = (const float4*)xb;
    for (int i = threadIdx.x; i < HH / 4; i += blockDim.x) {
        xs0[i] = xa4[i];
        xs1[i] = xb4[i];
    }
    __syncthreads();

    int warp = threadIdx.x >> 5;
    int lane = threadIdx.x & 31;
    int r = bb * 8 + warp;               // 8 warps per block, 1 row each
    if (r >= G3H) return;

    const float4* Wr = (const float4*)(W + (size_t)r * HH);
    float a0 = 0.f, a1 = 0.f;
#pragma unroll 8
    for (int i = 0; i < 32; i++) {
        float4 w = Wr[i * 32 + lane];
        float4 p = xs0[i * 32 + lane];
        float4 q = xs1[i * 32 + lane];
        a0 += w.x * p.x + w.y * p.y + w.z * p.z + w.w * p.w;
        a1 += w.x * q.x + w.y * q.y + w.z * q.z + w.w * q.w;
    }
#pragma unroll
    for (int o = 16; o; o >>= 1) {
        a0 += __shfl_xor_sync(0xffffffffu, a0, o);
        a1 += __shfl_xor_sync(0xffffffffu, a1, o);
    }
    if (lane == 0) {
        float bv = bias[r];
        out[r]        = a0 + bv;
        out[G3H + r]  = a1 + bv;
    }
}

// ---------------- GRU elementwise ----------------------------------------
__global__ void k_gru(const float* __restrict__ gc1w, const float* __restrict__ gc2w) {
    int idx = blockIdx.x * blockDim.x + threadIdx.x;
    if (idx >= 2 * HH) return;
    int b = idx >> 12;          // /4096
    int i = idx & (HH - 1);
    const float* gi = g_gi + b * G3H;
    const float* gh = g_gh + b * G3H;
    float hcur = (b ? gc2w : gc1w)[i];
    float r = 1.0f / (1.0f + expf(-(gi[i] + gh[i])));
    float z = 1.0f / (1.0f + expf(-(gi[HH + i] + gh[HH + i])));
    float n = tanhf(gi[2 * HH + i] + r * gh[2 * HH + i]);
    g_w[b * HH + i] = (1.0f - z) * n + z * hcur;
}

// ---------------- edge aggregation ---------------------------------------
// agg[dst] += out_norm[src] * x[src].  Warp handles 32 edges; each iteration
// processes 2 edges with 16 lanes x float4 each (red.global.add.v4.f32).
__global__ __launch_bounds__(256) void k_agg(
    const float* __restrict__ x_in, const int* __restrict__ src,
    const int* __restrict__ dst, int E, int use_h1)
{
    const float* x = use_h1 ? g_h1 : x_in;
    int gw   = (blockIdx.x * blockDim.x + threadIdx.x) >> 5;
    int lane = threadIdx.x & 31;
    long long base = (long long)gw * 32;
    if (base >= E) return;
    int cnt = (int)min((long long)32, (long long)E - base);

    int s = 0, d = 0;
    float on = 0.f;
    if (lane < cnt) {
        int e = (int)base + lane;
        s = src[e];
        d = dst[e];
        on = g_outn[s];
    }
    int half = lane >> 4;
    int li   = lane & 15;
    const float4* x4 = (const float4*)x;

#pragma unroll 4
    for (int j = 0; j < 16; j++) {
        int eoff = j + (half << 4);
        int   ss = __shfl_sync(0xffffffffu, s, eoff);
        int   dd = __shfl_sync(0xffffffffu, d, eoff);
        float no = __shfl_sync(0xffffffffu, on, eoff);
        if (eoff < cnt) {
            float4 v = x4[(size_t)ss * 16 + li];
            red_add_v4(&g_agg[(size_t)dd * 64 + li * 4],
                       v.x * no, v.y * no, v.z * no, v.w * no);
        }
    }
}

// ---------------- per-node 64x64 GEMM + norm + bias (+relu) --------------
// out[i,j] = act(in_norm[i] * sum_k agg[i,k]*W[k,j] + b[j])
__global__ __launch_bounds__(256) void k_gemm(
    const float* __restrict__ bias, float* __restrict__ dout,
    int N, int which, int relu, int to_out)
{
    __shared__ float Ws[DD * DD];
    __shared__ float bs[DD];
    const float* Wd = g_w + which * HH;
    for (int i = threadIdx.x; i < DD * DD; i += blockDim.x) Ws[i] = Wd[i];
    if (threadIdx.x < DD) bs[threadIdx.x] = bias[threadIdx.x];
    __syncthreads();

    float* out = to_out ? dout : g_h1;
    int lane = threadIdx.x & 31;
    int gw = (blockIdx.x * blockDim.x + threadIdx.x) >> 5;
    int tw = (gridDim.x * blockDim.x) >> 5;

    for (int row = gw; row < N; row += tw) {
        const float* ar = g_agg + (size_t)row * DD;
        float a0 = ar[lane];
        float a1 = ar[lane + 32];
        float acc0 = 0.f, acc1 = 0.f;
#pragma unroll
        for (int k = 0; k < 32; k++) {
            float ak = __shfl_sync(0xffffffffu, a0, k);
            acc0 += ak * Ws[k * 64 + lane];
            acc1 += ak * Ws[k * 64 + lane + 32];
        }
#pragma unroll
        for (int k = 0; k < 32; k++) {
            float ak = __shfl_sync(0xffffffffu, a1, k);
            acc0 += ak * Ws[(k + 32) * 64 + lane];
            acc1 += ak * Ws[(k + 32) * 64 + lane + 32];
        }
        float sN = g_inn[row];
        float r0 = acc0 * sN + bs[lane];
        float r1 = acc1 * sN + bs[lane + 32];
        if (relu) { r0 = fmaxf(r0, 0.f); r1 = fmaxf(r1, 0.f); }
        out[(size_t)row * DD + lane]      = r0;
        out[(size_t)row * DD + lane + 32] = r1;
    }
}

// ---------------- launch --------------------------------------------------
extern "C" void kernel_launch(void* const* d_in, const int* in_sizes, int n_in,
                              void* d_out, int out_size)
{
    const float* node  = (const float*)d_in[0];
    const float* gc1w  = (const float*)d_in[1];
    const float* gc2w  = (const float*)d_in[2];
    const float* gc1b  = (const float*)d_in[3];
    const float* gc2b  = (const float*)d_in[4];
    const float* prev1 = (const float*)d_in[5];
    const float* prev2 = (const float*)d_in[6];
    const float* Wih   = (const float*)d_in[7];
    const float* Whh   = (const float*)d_in[8];
    const float* bih   = (const float*)d_in[9];
    const float* bhh   = (const float*)d_in[10];
    const int*   src   = (const int*)d_in[11];
    const int*   dst   = (const int*)d_in[12];
    float* out = (float*)d_out;

    int N = in_sizes[0] / DD;
    int E = in_sizes[11];

    // degrees + norms
    k_zero_deg<<<(2 * N + 255) / 256, 256>>>(N);
    k_degree<<<2048, 256>>>(src, dst, E, N);
    k_norm<<<(N + 255) / 256, 256>>>(N);

    // GRU weight evolution (batched GEMV over both matrices, both inputs)
    k_gemv<<<2 * (G3H / 8), 256>>>(Wih, Whh, prev1, prev2, gc1w, gc2w, bih, bhh);
    k_gru<<<(2 * HH + 255) / 256, 256>>>(gc1w, gc2w);

    int aggWarps  = (E + 31) / 32;
    int aggBlocks = (aggWarps + 7) / 8;

    // layer 1
    k_zero_agg<<<2048, 256>>>(N);
    k_agg<<<aggBlocks, 256>>>(node, src, dst, E, 0);
    k_gemm<<<1024, 256>>>(gc1b, out, N, 0, 1, 0);

    // layer 2
    k_zero_agg<<<2048, 256>>>(N);
    k_agg<<<aggBlocks, 256>>>(node, src, dst, E, 1);
    k_gemm<<<1024, 256>>>(gc2b, out, N, 1, 0, 1);
}